// round 8
// baseline (speedup 1.0000x reference)
#include <cuda_runtime.h>

#define N_SAMPLES 16384
#define DIM       1024
#define F4_ROW    (DIM / 4)             // 256 float4 per row
#define MARGIN    1.0f
#define EPSF      1e-6f
#define BLOCK     256
#define WARPS     (BLOCK / 32)          // 8 warps
#define SPB       (WARPS / 2)           // 4 samples per block (2 warps/sample)
#define GRID      (N_SAMPLES / SPB)     // 4096 blocks

__device__ double g_acc;      // zero at load; reset by last block each call
__device__ unsigned g_count;

__device__ __forceinline__ float dot4(float4 u, float4 v) {
    return u.x*v.x + u.y*v.y + u.z*v.z + u.w*v.w;
}

__global__ __launch_bounds__(BLOCK, 4)   // cap 64 regs -> 32 warps/SM
void cl_half_kernel(const float* __restrict__ emb,
                    const int* __restrict__ pos_idx,
                    const int* __restrict__ neg_idx,
                    float* __restrict__ out)
{
    const int wid  = threadIdx.x >> 5;
    const int lane = threadIdx.x & 31;
    const int s    = wid >> 1;                   // sample slot in block (0..3)
    const int h    = wid & 1;                    // which half-row this warp owns
    const int i    = blockIdx.x * SPB + s;       // global sample

    const int p = pos_idx[i];
    const int n = neg_idx[i];

    const float4* ra = (const float4*)(emb + (size_t)i * DIM) + h * (F4_ROW / 2);
    const float4* rb = (const float4*)(emb + (size_t)p * DIM) + h * (F4_ROW / 2);
    const float4* rc = (const float4*)(emb + (size_t)n * DIM) + h * (F4_ROW / 2);

    // One batch of 12 independent LDG.128 (half of each of the 3 rows).
    float4 A[4], B[4], C[4];
    #pragma unroll
    for (int c = 0; c < 4; c++) {
        const int idx = c * 32 + lane;
        A[c] = ra[idx];
        B[c] = rb[idx];
        C[c] = rc[idx];
    }

    float sa = 0.f, sb = 0.f, sc = 0.f, dab = 0.f, dac = 0.f;
    #pragma unroll
    for (int c = 0; c < 4; c++) {
        sa  += dot4(A[c], A[c]);
        sb  += dot4(B[c], B[c]);
        sc  += dot4(C[c], C[c]);
        dab += dot4(A[c], B[c]);
        dac += dot4(A[c], C[c]);
    }

    #pragma unroll
    for (int o = 16; o > 0; o >>= 1) {
        sa  += __shfl_xor_sync(0xffffffffu, sa,  o);
        sb  += __shfl_xor_sync(0xffffffffu, sb,  o);
        sc  += __shfl_xor_sync(0xffffffffu, sc,  o);
        dab += __shfl_xor_sync(0xffffffffu, dab, o);
        dac += __shfl_xor_sync(0xffffffffu, dac, o);
    }

    __shared__ float part[WARPS][5];
    __shared__ double samp_loss[SPB];
    if (lane == 0) {
        part[wid][0] = sa;  part[wid][1] = sb;  part[wid][2] = sc;
        part[wid][3] = dab; part[wid][4] = dac;
    }
    __syncthreads();

    // Even warp of each pair combines halves and computes the sample loss.
    if (h == 0 && lane == 0) {
        const float fsa  = part[wid][0] + part[wid + 1][0];
        const float fsb  = part[wid][1] + part[wid + 1][1];
        const float fsc  = part[wid][2] + part[wid + 1][2];
        const float fdab = part[wid][3] + part[wid + 1][3];
        const float fdac = part[wid][4] + part[wid + 1][4];

        // F.normalize: 1/max(||x||, eps)
        const float ia = 1.0f / fmaxf(sqrtf(fsa), EPSF);
        const float ib = 1.0f / fmaxf(sqrtf(fsb), EPSF);
        const float ic = 1.0f / fmaxf(sqrtf(fsc), EPSF);

        // ||u - v + eps||^2 expanded (mean-zero eps cross-term dropped)
        const float de2 = (float)DIM * EPSF * EPSF;
        float dp = fsa*ia*ia + fsb*ib*ib - 2.0f*fdab*ia*ib + de2;
        float dn = fsa*ia*ia + fsc*ic*ic - 2.0f*fdac*ia*ic + de2;
        dp = fmaxf(dp, 0.0f);
        dn = fmaxf(dn, 0.0f);

        const float d_pos = sqrtf(dp) + EPSF;    // pairwise_distance + module eps
        const float d_neg = sqrtf(dn) + EPSF;

        const float lp = d_pos * d_pos;
        const float tn = fmaxf(MARGIN - d_neg, EPSF);
        samp_loss[s] = (double)(lp + tn * tn);
    }
    __syncthreads();

    if (threadIdx.x == 0) {
        double blk = 0.0;
        #pragma unroll
        for (int k = 0; k < SPB; k++) blk += samp_loss[k];

        atomicAdd(&g_acc, blk);
        __threadfence();
        unsigned done = atomicAdd(&g_count, 1u);
        if (done == GRID - 1u) {
            out[0] = (float)(g_acc / (2.0 * (double)N_SAMPLES));
            g_acc = 0.0;      // reset for next graph replay
            g_count = 0u;
            __threadfence();
        }
    }
}

extern "C" void kernel_launch(void* const* d_in, const int* in_sizes, int n_in,
                              void* d_out, int out_size)
{
    const float* emb = (const float*)d_in[0];
    // d_in[1] = labels (int32) — unused by the loss
    const int*   pos = (const int*)d_in[2];
    const int*   neg = (const int*)d_in[3];
    float* out = (float*)d_out;

    cl_half_kernel<<<GRID, BLOCK>>>(emb, pos, neg, out);
}

// round 9
// speedup vs baseline: 1.2149x; 1.2149x over previous
#include <cuda_runtime.h>

#define N_SAMPLES 16384
#define DIM       1024
#define CHUNKS    (DIM / 4 / 32)        // 8 float4-chunks per lane per row
#define MARGIN    1.0f
#define EPSF      1e-6f
#define BLOCK     256
#define WARPS     (BLOCK / 32)          // 8 warps
#define SPW       2                     // samples per warp
#define SPB       (WARPS * SPW)         // 16 samples per block
#define GRID      (N_SAMPLES / SPB)     // 1024 blocks

__device__ double g_acc;      // zero at load; reset by last block each call
__device__ unsigned g_count;

__device__ __forceinline__ float dot4(float4 u, float4 v) {
    return u.x*v.x + u.y*v.y + u.z*v.z + u.w*v.w;
}

__global__ __launch_bounds__(BLOCK)
void cl_dot2_kernel(const float* __restrict__ emb,
                    const int* __restrict__ pos_idx,
                    const int* __restrict__ neg_idx,
                    float* __restrict__ out)
{
    const int wid  = threadIdx.x >> 5;
    const int lane = threadIdx.x & 31;
    // two samples per warp
    const int i0 = blockIdx.x * SPB + wid * SPW;
    const int i1 = i0 + 1;

    const int p0 = pos_idx[i0], n0 = neg_idx[i0];
    const int p1 = pos_idx[i1], n1 = neg_idx[i1];

    const float4* ra0 = (const float4*)(emb + (size_t)i0 * DIM);
    const float4* rb0 = (const float4*)(emb + (size_t)p0 * DIM);
    const float4* rc0 = (const float4*)(emb + (size_t)n0 * DIM);
    const float4* ra1 = (const float4*)(emb + (size_t)i1 * DIM);
    const float4* rb1 = (const float4*)(emb + (size_t)p1 * DIM);
    const float4* rc1 = (const float4*)(emb + (size_t)n1 * DIM);

    float sa0 = 0.f, sb0 = 0.f, sc0 = 0.f, dab0 = 0.f, dac0 = 0.f;
    float sa1 = 0.f, sb1 = 0.f, sc1 = 0.f, dab1 = 0.f, dac1 = 0.f;

    #pragma unroll
    for (int c = 0; c < CHUNKS; c++) {
        const int idx = c * 32 + lane;           // coalesced 512B per chunk-load
        // 6 independent load streams per warp
        float4 a0 = ra0[idx];
        float4 b0 = rb0[idx];
        float4 c0 = rc0[idx];
        float4 a1 = ra1[idx];
        float4 b1 = rb1[idx];
        float4 c1 = rc1[idx];

        sa0  += dot4(a0, a0);
        sb0  += dot4(b0, b0);
        sc0  += dot4(c0, c0);
        dab0 += dot4(a0, b0);
        dac0 += dot4(a0, c0);

        sa1  += dot4(a1, a1);
        sb1  += dot4(b1, b1);
        sc1  += dot4(c1, c1);
        dab1 += dot4(a1, b1);
        dac1 += dot4(a1, c1);
    }

    #pragma unroll
    for (int o = 16; o > 0; o >>= 1) {
        sa0  += __shfl_xor_sync(0xffffffffu, sa0,  o);
        sb0  += __shfl_xor_sync(0xffffffffu, sb0,  o);
        sc0  += __shfl_xor_sync(0xffffffffu, sc0,  o);
        dab0 += __shfl_xor_sync(0xffffffffu, dab0, o);
        dac0 += __shfl_xor_sync(0xffffffffu, dac0, o);
        sa1  += __shfl_xor_sync(0xffffffffu, sa1,  o);
        sb1  += __shfl_xor_sync(0xffffffffu, sb1,  o);
        sc1  += __shfl_xor_sync(0xffffffffu, sc1,  o);
        dab1 += __shfl_xor_sync(0xffffffffu, dab1, o);
        dac1 += __shfl_xor_sync(0xffffffffu, dac1, o);
    }

    __shared__ double warp_loss[WARPS];
    if (lane == 0) {
        const float de2 = (float)DIM * EPSF * EPSF;

        // sample 0
        float ia = 1.0f / fmaxf(sqrtf(sa0), EPSF);
        float ib = 1.0f / fmaxf(sqrtf(sb0), EPSF);
        float ic = 1.0f / fmaxf(sqrtf(sc0), EPSF);
        float dp = fmaxf(sa0*ia*ia + sb0*ib*ib - 2.0f*dab0*ia*ib + de2, 0.0f);
        float dn = fmaxf(sa0*ia*ia + sc0*ic*ic - 2.0f*dac0*ia*ic + de2, 0.0f);
        float d_pos = sqrtf(dp) + EPSF;
        float d_neg = sqrtf(dn) + EPSF;
        float tn = fmaxf(MARGIN - d_neg, EPSF);
        double acc = (double)(d_pos * d_pos + tn * tn);

        // sample 1
        ia = 1.0f / fmaxf(sqrtf(sa1), EPSF);
        ib = 1.0f / fmaxf(sqrtf(sb1), EPSF);
        ic = 1.0f / fmaxf(sqrtf(sc1), EPSF);
        dp = fmaxf(sa1*ia*ia + sb1*ib*ib - 2.0f*dab1*ia*ib + de2, 0.0f);
        dn = fmaxf(sa1*ia*ia + sc1*ic*ic - 2.0f*dac1*ia*ic + de2, 0.0f);
        d_pos = sqrtf(dp) + EPSF;
        d_neg = sqrtf(dn) + EPSF;
        tn = fmaxf(MARGIN - d_neg, EPSF);
        acc += (double)(d_pos * d_pos + tn * tn);

        warp_loss[wid] = acc;
    }
    __syncthreads();

    if (threadIdx.x == 0) {
        double blk = 0.0;
        #pragma unroll
        for (int w = 0; w < WARPS; w++) blk += warp_loss[w];

        atomicAdd(&g_acc, blk);
        __threadfence();
        unsigned done = atomicAdd(&g_count, 1u);
        if (done == GRID - 1u) {
            out[0] = (float)(g_acc / (2.0 * (double)N_SAMPLES));
            g_acc = 0.0;      // reset for next graph replay
            g_count = 0u;
            __threadfence();
        }
    }
}

extern "C" void kernel_launch(void* const* d_in, const int* in_sizes, int n_in,
                              void* d_out, int out_size)
{
    const float* emb = (const float*)d_in[0];
    // d_in[1] = labels (int32) — unused by the loss
    const int*   pos = (const int*)d_in[2];
    const int*   neg = (const int*)d_in[3];
    float* out = (float*)d_out;

    cl_dot2_kernel<<<GRID, BLOCK>>>(emb, pos, neg, out);
}

// round 10
// speedup vs baseline: 1.2503x; 1.0292x over previous
#include <cuda_runtime.h>

#define N_SAMPLES 16384
#define DIM       1024
#define CHUNKS    (DIM / 4 / 32)        // 8 float4-chunks per lane per row
#define MARGIN    1.0f
#define EPSF      1e-6f
#define BLOCK     256
#define WARPS     (BLOCK / 32)          // 8 warps
#define SPW       2                     // samples per warp
#define SPB       (WARPS * SPW)         // 16 samples per block
#define GRID      (N_SAMPLES / SPB)     // 1024 blocks

__device__ double g_acc;      // zero at load; reset by last block each call
__device__ unsigned g_count;

__device__ __forceinline__ float dot4(float4 u, float4 v) {
    return u.x*v.x + u.y*v.y + u.z*v.z + u.w*v.w;
}

__global__ __launch_bounds__(BLOCK)
void cl_dot2_kernel(const float* __restrict__ emb,
                    const int* __restrict__ pos_idx,
                    const int* __restrict__ neg_idx,
                    float* __restrict__ out)
{
    const int wid  = threadIdx.x >> 5;
    const int lane = threadIdx.x & 31;
    // two samples per warp
    const int i0 = blockIdx.x * SPB + wid * SPW;
    const int i1 = i0 + 1;

    const int p0 = pos_idx[i0], n0 = neg_idx[i0];
    const int p1 = pos_idx[i1], n1 = neg_idx[i1];

    const float4* ra0 = (const float4*)(emb + (size_t)i0 * DIM);
    const float4* rb0 = (const float4*)(emb + (size_t)p0 * DIM);
    const float4* rc0 = (const float4*)(emb + (size_t)n0 * DIM);
    const float4* ra1 = (const float4*)(emb + (size_t)i1 * DIM);
    const float4* rb1 = (const float4*)(emb + (size_t)p1 * DIM);
    const float4* rc1 = (const float4*)(emb + (size_t)n1 * DIM);

    float sa0 = 0.f, sb0 = 0.f, sc0 = 0.f, dab0 = 0.f, dac0 = 0.f;
    float sa1 = 0.f, sb1 = 0.f, sc1 = 0.f, dab1 = 0.f, dac1 = 0.f;

    #pragma unroll
    for (int c = 0; c < CHUNKS; c++) {
        const int idx = c * 32 + lane;           // coalesced 512B per chunk-load
        // 6 independent load streams per warp
        float4 a0 = ra0[idx];
        float4 b0 = rb0[idx];
        float4 c0 = rc0[idx];
        float4 a1 = ra1[idx];
        float4 b1 = rb1[idx];
        float4 c1 = rc1[idx];

        sa0  += dot4(a0, a0);
        sb0  += dot4(b0, b0);
        sc0  += dot4(c0, c0);
        dab0 += dot4(a0, b0);
        dac0 += dot4(a0, c0);

        sa1  += dot4(a1, a1);
        sb1  += dot4(b1, b1);
        sc1  += dot4(c1, c1);
        dab1 += dot4(a1, b1);
        dac1 += dot4(a1, c1);
    }

    #pragma unroll
    for (int o = 16; o > 0; o >>= 1) {
        sa0  += __shfl_xor_sync(0xffffffffu, sa0,  o);
        sb0  += __shfl_xor_sync(0xffffffffu, sb0,  o);
        sc0  += __shfl_xor_sync(0xffffffffu, sc0,  o);
        dab0 += __shfl_xor_sync(0xffffffffu, dab0, o);
        dac0 += __shfl_xor_sync(0xffffffffu, dac0, o);
        sa1  += __shfl_xor_sync(0xffffffffu, sa1,  o);
        sb1  += __shfl_xor_sync(0xffffffffu, sb1,  o);
        sc1  += __shfl_xor_sync(0xffffffffu, sc1,  o);
        dab1 += __shfl_xor_sync(0xffffffffu, dab1, o);
        dac1 += __shfl_xor_sync(0xffffffffu, dac1, o);
    }

    __shared__ double warp_loss[WARPS];
    if (lane == 0) {
        const float de2 = (float)DIM * EPSF * EPSF;

        // sample 0
        float ia = 1.0f / fmaxf(sqrtf(sa0), EPSF);
        float ib = 1.0f / fmaxf(sqrtf(sb0), EPSF);
        float ic = 1.0f / fmaxf(sqrtf(sc0), EPSF);
        float dp = fmaxf(sa0*ia*ia + sb0*ib*ib - 2.0f*dab0*ia*ib + de2, 0.0f);
        float dn = fmaxf(sa0*ia*ia + sc0*ic*ic - 2.0f*dac0*ia*ic + de2, 0.0f);
        float d_pos = sqrtf(dp) + EPSF;
        float d_neg = sqrtf(dn) + EPSF;
        float tn = fmaxf(MARGIN - d_neg, EPSF);
        double acc = (double)(d_pos * d_pos + tn * tn);

        // sample 1
        ia = 1.0f / fmaxf(sqrtf(sa1), EPSF);
        ib = 1.0f / fmaxf(sqrtf(sb1), EPSF);
        ic = 1.0f / fmaxf(sqrtf(sc1), EPSF);
        dp = fmaxf(sa1*ia*ia + sb1*ib*ib - 2.0f*dab1*ia*ib + de2, 0.0f);
        dn = fmaxf(sa1*ia*ia + sc1*ic*ic - 2.0f*dac1*ia*ic + de2, 0.0f);
        d_pos = sqrtf(dp) + EPSF;
        d_neg = sqrtf(dn) + EPSF;
        tn = fmaxf(MARGIN - d_neg, EPSF);
        acc += (double)(d_pos * d_pos + tn * tn);

        warp_loss[wid] = acc;
    }
    __syncthreads();

    if (threadIdx.x == 0) {
        double blk = 0.0;
        #pragma unroll
        for (int w = 0; w < WARPS; w++) blk += warp_loss[w];

        atomicAdd(&g_acc, blk);
        __threadfence();
        unsigned done = atomicAdd(&g_count, 1u);
        if (done == GRID - 1u) {
            out[0] = (float)(g_acc / (2.0 * (double)N_SAMPLES));
            g_acc = 0.0;      // reset for next graph replay
            g_count = 0u;
            __threadfence();
        }
    }
}

extern "C" void kernel_launch(void* const* d_in, const int* in_sizes, int n_in,
                              void* d_out, int out_size)
{
    const float* emb = (const float*)d_in[0];
    // d_in[1] = labels (int32) — unused by the loss
    const int*   pos = (const int*)d_in[2];
    const int*   neg = (const int*)d_in[3];
    float* out = (float*)d_out;

    cl_dot2_kernel<<<GRID, BLOCK>>>(emb, pos, neg, out);
}